// round 6
// baseline (speedup 1.0000x reference)
#include <cuda_runtime.h>
#include <cuda_bf16.h>
#include <cstdint>
#include <math.h>

#define EMBED  1024
#define HIDDEN 512
#define NB     4
#define SQ     4096
#define SKV    4096
#define MTOK   (NB * SQ)   // 16384

typedef __nv_bfloat16 bf16;
typedef __nv_bfloat162 bf162;

// ---------------- scratch (static device arrays; no allocations) ----------------
__device__ bf16 g_qfh [(size_t)MTOK * EMBED];        // bf16 q_feat (hi)
__device__ bf16 g_kvh [(size_t)MTOK * EMBED];        // bf16 kv_feat (hi)
__device__ bf16 g_Qh  [(size_t)MTOK * HIDDEN];       // bf16 Q
__device__ bf16 g_Kh  [(size_t)MTOK * HIDDEN];       // bf16 K
__device__ bf16 g_VT  [(size_t)HIDDEN * MTOK];       // bf16 V^T [H, tokens]
__device__ bf16 g_S   [(size_t)NB * SQ * SKV];       // unnormalized exp-scores
__device__ float g_Zi [MTOK];                        // 1/rowsum
__device__ bf16 g_Ch  [(size_t)MTOK * HIDDEN];       // bf16 ctx
__device__ bf16 g_O1s [(size_t)MTOK * 3 * EMBED];    // A-split O1 [hi|lo|hi]
__device__ float g_O2 [(size_t)MTOK * EMBED];        // fp32 pre-LN
__device__ bf16 g_Wq1 [(size_t)HIDDEN * EMBED];      // bf16 Wq^T hi
__device__ bf16 g_Wk1 [(size_t)HIDDEN * EMBED];
__device__ bf16 g_Wv1 [(size_t)HIDDEN * EMBED];
__device__ bf16 g_Wo1 [(size_t)EMBED * HIDDEN];      // bf16 Wo^T hi
__device__ bf16 g_Wfc3[(size_t)EMBED * 3 * EMBED];   // B-split x3 Wfc^T [hi|hi|lo]

// ================= helpers =================
__device__ __forceinline__ uint32_t smem_u32(const void* p) {
    return (uint32_t)__cvta_generic_to_shared((void*)p);
}
#define SWZ128(o) ((o) ^ (((o) >> 3) & 0x70))

__device__ __forceinline__ void cpa16(uint32_t s, const void* g) {
    asm volatile("cp.async.cg.shared.global [%0], [%1], 16;" :: "r"(s), "l"(g));
}
__device__ __forceinline__ void cpa_commit() {
    asm volatile("cp.async.commit_group;" ::: "memory");
}
template <int N> __device__ __forceinline__ void cpa_wait() {
    asm volatile("cp.async.wait_group %0;" :: "n"(N) : "memory");
}
__device__ __forceinline__ void ldsm_x4(uint32_t a, uint32_t& r0, uint32_t& r1,
                                        uint32_t& r2, uint32_t& r3) {
    asm volatile("ldmatrix.sync.aligned.m8n8.x4.shared.b16 {%0,%1,%2,%3}, [%4];"
                 : "=r"(r0), "=r"(r1), "=r"(r2), "=r"(r3) : "r"(a));
}
__device__ __forceinline__ void mma16816(float* c, const uint32_t* a, const uint32_t* b) {
    asm volatile("mma.sync.aligned.m16n8k16.row.col.f32.bf16.bf16.f32 "
                 "{%0,%1,%2,%3}, {%4,%5,%6,%7}, {%8,%9}, {%0,%1,%2,%3};"
                 : "+f"(c[0]), "+f"(c[1]), "+f"(c[2]), "+f"(c[3])
                 : "r"(a[0]), "r"(a[1]), "r"(a[2]), "r"(a[3]), "r"(b[0]), "r"(b[1]));
}
__device__ __forceinline__ void split_pair(float x, float y, bf162& h, bf162& l) {
    h = __floats2bfloat162_rn(x, y);
    l = __floats2bfloat162_rn(x - __bfloat162float(h.x), y - __bfloat162float(h.y));
}
__device__ __forceinline__ float ex2_mufu(float t) {
    float r;
    asm("ex2.approx.f32 %0, %1;" : "=f"(r) : "f"(t));
    return r;
}

// ================= bf16 NT GEMM =================
// D[m,n] = sum_k A[m,k]*B[n,k]; A row-stride lda, B row-stride ldb (bf16, rm).
// CTA tile 128(M) x 256(N), warp tile 64x64, 8 warps, K-step 64, 3-stage cp.async.
// MODE 0: fp32 store
// MODE 3: +bias[col]+res[row,col] (fp32) -> A-split x3 bf16 store [hi|lo|hi]
// MODE 4: plain bf16 store
// MODE 5: acc * rowscale[z*sAux + r] -> plain bf16 store
// MODE 6: exp2(acc * escale2) -> plain bf16 store
#define STAGE_B 49152                 // 16KB A + 32KB B
#define GSMEM   (3 * STAGE_B)         // 147456

template <int MODE>
__global__ void __launch_bounds__(256, 1)
gemm_nt(const bf16* __restrict__ Ag, const bf16* __restrict__ Bg,
        void* __restrict__ Cg, int Kp, int lda, int ldb, int ldc,
        long long sA, long long sB, long long sC,
        const float* __restrict__ aux1, const float* __restrict__ aux2,
        long long sAux, float escale2)
{
    extern __shared__ char smc[];
    const uint32_t sm0 = smem_u32(smc);
    const int tid  = threadIdx.x;
    const int wid  = tid >> 5;
    const int lane = tid & 31;
    const int wm = wid >> 2;        // 0..1 (64 rows each)
    const int wn = wid & 3;         // 0..3 (64 cols each)
    const int m0 = blockIdx.y * 128;
    const int n0 = blockIdx.x * 256;

    Ag += (long long)blockIdx.z * sA;
    Bg += (long long)blockIdx.z * sB;

    const bf16* Abase = Ag + (long long)m0 * lda;
    const bf16* Bbase = Bg + (long long)n0 * ldb;

    const int r8 = tid >> 3;            // 0..31
    const int c8 = tid & 7;             // 16B chunk

    float acc[4][8][4];
    #pragma unroll
    for (int a = 0; a < 4; a++)
        #pragma unroll
        for (int b = 0; b < 8; b++)
            #pragma unroll
            for (int c = 0; c < 4; c++) acc[a][b][c] = 0.0f;

    const int KT = Kp >> 6;

    auto load_stage = [&](int st, int kt) {
        const uint32_t sa = sm0 + st * STAGE_B;
        const uint32_t sb = sa + 16384;
        const int kofs = kt * 64;
        #pragma unroll
        for (int i = 0; i < 4; i++) {
            const int row = r8 + i * 32;
            const uint32_t soff = SWZ128((uint32_t)(row * 128 + c8 * 16));
            cpa16(sa + soff, Abase + (long long)row * lda + kofs + c8 * 8);
        }
        #pragma unroll
        for (int j = 0; j < 8; j++) {
            const int row = r8 + j * 32;
            const uint32_t soff = SWZ128((uint32_t)(row * 128 + c8 * 16));
            cpa16(sb + soff, Bbase + (long long)row * ldb + kofs + c8 * 8);
        }
    };

    load_stage(0, 0); cpa_commit();
    load_stage(1, 1); cpa_commit();

    uint32_t fa[2][4][4];
    uint32_t fb[2][8][2];

    auto ld_frags = [&](int buf, uint32_t sa, uint32_t sb, int ks) {
        const int bcol = ks * 32 + ((lane >> 4) << 4);
        #pragma unroll
        for (int mt = 0; mt < 4; mt++) {
            const int row = wm * 64 + mt * 16 + (lane & 15);
            ldsm_x4(sa + SWZ128((uint32_t)(row * 128 + bcol)),
                    fa[buf][mt][0], fa[buf][mt][1], fa[buf][mt][2], fa[buf][mt][3]);
        }
        #pragma unroll
        for (int np = 0; np < 4; np++) {
            const int row = wn * 64 + np * 16 + (lane & 15);
            uint32_t r0, r1, r2, r3;
            ldsm_x4(sb + SWZ128((uint32_t)(row * 128 + bcol)), r0, r1, r2, r3);
            fb[buf][2*np][0]   = r0; fb[buf][2*np][1]   = r2;
            fb[buf][2*np+1][0] = r1; fb[buf][2*np+1][1] = r3;
        }
    };

    int st = 0;                // stage for iteration kt
    for (int kt = 0; kt < KT; ++kt) {
        cpa_wait<1>();
        __syncthreads();

        const uint32_t sa = sm0 + st * STAGE_B;
        const uint32_t sb = sa + 16384;

        ld_frags(0, sa, sb, 0);
        #pragma unroll
        for (int ks = 0; ks < 4; ks++) {
            const int cur = ks & 1;
            if (ks < 3) ld_frags(cur ^ 1, sa, sb, ks + 1);
            #pragma unroll
            for (int mt = 0; mt < 4; mt++)
                #pragma unroll
                for (int nt = 0; nt < 8; nt++)
                    mma16816(acc[mt][nt], fa[cur][mt], fb[cur][nt]);
        }

        if (kt + 2 < KT) {
            int nst = st + 2; if (nst >= 3) nst -= 3;
            load_stage(nst, kt + 2);
        }
        cpa_commit();
        if (++st == 3) st = 0;
    }

    // -------- epilogue --------
    const int ld3 = 3 * ldc;
    const float* rs = (MODE == 5) ? (aux1 + (long long)blockIdx.z * sAux) : nullptr;

    #pragma unroll
    for (int mt = 0; mt < 4; mt++) {
        const int r0 = m0 + wm * 64 + mt * 16 + (lane >> 2);
        const int r1 = r0 + 8;
        float rs0 = 1.0f, rs1 = 1.0f;
        if (MODE == 5) { rs0 = rs[r0]; rs1 = rs[r1]; }
        #pragma unroll
        for (int nt = 0; nt < 8; nt++) {
            const int c = n0 + wn * 64 + nt * 8 + (lane & 3) * 2;
            float x0 = acc[mt][nt][0], y0 = acc[mt][nt][1];
            float x1 = acc[mt][nt][2], y1 = acc[mt][nt][3];
            if (MODE == 5) { x0 *= rs0; y0 *= rs0; x1 *= rs1; y1 *= rs1; }
            if (MODE == 6) {
                x0 = ex2_mufu(x0 * escale2); y0 = ex2_mufu(y0 * escale2);
                x1 = ex2_mufu(x1 * escale2); y1 = ex2_mufu(y1 * escale2);
            }
            if (MODE == 3) {
                const float2 bv = *(const float2*)&aux1[c];
                const float2 q0 = *(const float2*)&aux2[(long long)r0 * ldc + c];
                const float2 q1 = *(const float2*)&aux2[(long long)r1 * ldc + c];
                x0 += bv.x + q0.x; y0 += bv.y + q0.y;
                x1 += bv.x + q1.x; y1 += bv.y + q1.y;
                bf16* Cs = (bf16*)Cg;
                bf162 h0, l0, h1, l1;
                split_pair(x0, y0, h0, l0);
                split_pair(x1, y1, h1, l1);
                bf16* p0 = Cs + (long long)r0 * ld3 + c;
                bf16* p1 = Cs + (long long)r1 * ld3 + c;
                *(bf162*)(p0) = h0; *(bf162*)(p0 + ldc) = l0; *(bf162*)(p0 + 2*ldc) = h0;
                *(bf162*)(p1) = h1; *(bf162*)(p1 + ldc) = l1; *(bf162*)(p1 + 2*ldc) = h1;
            } else if (MODE == 0) {
                float* Cf = (float*)Cg + (long long)blockIdx.z * sC;
                *(float2*)&Cf[(long long)r0 * ldc + c] = make_float2(x0, y0);
                *(float2*)&Cf[(long long)r1 * ldc + c] = make_float2(x1, y1);
            } else {
                bf16* Cb = (bf16*)Cg + (long long)blockIdx.z * sC;
                *(bf162*)&Cb[(long long)r0 * ldc + c] = __floats2bfloat162_rn(x0, y0);
                *(bf162*)&Cb[(long long)r1 * ldc + c] = __floats2bfloat162_rn(x1, y1);
            }
        }
    }
}

// ============ fp32 -> bf16 hi convert (elementwise) ============
__global__ void conv_hi(const float* __restrict__ X, bf16* __restrict__ Y)
{
    const long long i4 = (long long)blockIdx.x * blockDim.x + threadIdx.x;
    float4 v = ((const float4*)X)[i4];
    ((bf162*)Y)[i4 * 2]     = __floats2bfloat162_rn(v.x, v.y);
    ((bf162*)Y)[i4 * 2 + 1] = __floats2bfloat162_rn(v.z, v.w);
}

// ============ transpose + bf16 hi: In[R,C] fp32 -> Out[C,R] bf16 ============
__global__ void w3tr(const float* __restrict__ A0, const float* __restrict__ A1,
                     const float* __restrict__ A2,
                     bf16* __restrict__ B0, bf16* __restrict__ B1,
                     bf16* __restrict__ B2, int R, int C)
{
    const float* In = (blockIdx.z == 0) ? A0 : (blockIdx.z == 1) ? A1 : A2;
    bf16* Out = (blockIdx.z == 0) ? B0 : (blockIdx.z == 1) ? B1 : B2;
    __shared__ float t[32][33];
    const int bx = blockIdx.x * 32;   // C
    const int by = blockIdx.y * 32;   // R
    const int tx = threadIdx.x, ty = threadIdx.y;
    #pragma unroll
    for (int i = ty; i < 32; i += 8)
        t[i][tx] = In[(long long)(by + i) * C + bx + tx];
    __syncthreads();
    #pragma unroll
    for (int i = ty; i < 32; i += 8)
        Out[(long long)(bx + i) * R + by + tx] = __float2bfloat16(t[tx][i]);
}

// ============ B-split x3 + transpose: In[R,C] fp32 -> Out[C,3R] (hi,hi,lo) =======
__global__ void bsplit3_tr(const float* __restrict__ In, bf16* __restrict__ Out,
                           int R, int C)
{
    __shared__ float t[32][33];
    const int bx = blockIdx.x * 32;
    const int by = blockIdx.y * 32;
    const int tx = threadIdx.x, ty = threadIdx.y;
    #pragma unroll
    for (int i = ty; i < 32; i += 8)
        t[i][tx] = In[(long long)(by + i) * C + bx + tx];
    __syncthreads();
    #pragma unroll
    for (int i = ty; i < 32; i += 8) {
        const float v = t[tx][i];
        const bf16 h = __float2bfloat16(v);
        const bf16 l = __float2bfloat16(v - __bfloat162float(h));
        const long long ro = (long long)(bx + i) * (3LL * R) + by + tx;
        Out[ro] = h; Out[ro + R] = h; Out[ro + 2LL * R] = l;
    }
}

// ================= reductions =================
__device__ __forceinline__ float blockReduceSum(float v, float* sh)
{
    const int t = threadIdx.x;
    #pragma unroll
    for (int o = 16; o; o >>= 1) v += __shfl_xor_sync(0xFFFFFFFFu, v, o);
    if ((t & 31) == 0) sh[t >> 5] = v;
    __syncthreads();
    if (t < 32) {
        float r = (t < 8) ? sh[t] : 0.0f;
        #pragma unroll
        for (int o = 4; o; o >>= 1) r += __shfl_xor_sync(0xFFFFFFFFu, r, o);
        if (t == 0) sh[0] = r;
    }
    __syncthreads();
    float r = sh[0];
    __syncthreads();
    return r;
}

// ===== row sums of unnormalized exp-scores -> Zinv =====
__global__ void sumexp_kernel(const bf16* __restrict__ S, float* __restrict__ Zi)
{
    const bf162* p = (const bf162*)(S + (long long)blockIdx.x * SKV);
    const int t = threadIdx.x;
    __shared__ float sh[32];
    float s = 0.0f;
    #pragma unroll
    for (int i = 0; i < 8; i++) {
        float2 v = __bfloat1622float2(p[t + 256 * i]);
        s += v.x + v.y;
    }
    s = blockReduceSum(s, sh);
    if (t == 0) Zi[blockIdx.x] = 1.0f / s;
}

// ================= layernorm =================
__global__ void layernorm_kernel(const float* __restrict__ X,
                                 const float* __restrict__ gamma,
                                 const float* __restrict__ beta,
                                 float* __restrict__ Y)
{
    const float* x = X + (long long)blockIdx.x * EMBED;
    float*       y = Y + (long long)blockIdx.x * EMBED;
    const int t = threadIdx.x;
    __shared__ float sh[32];

    float4 v = *(const float4*)&x[t * 4];
    float s = v.x + v.y + v.z + v.w;
    s = blockReduceSum(s, sh);
    const float mu = s * (1.0f / EMBED);

    float dx = v.x - mu, dy = v.y - mu, dz = v.z - mu, dw = v.w - mu;
    float sq = dx * dx + dy * dy + dz * dz + dw * dw;
    sq = blockReduceSum(sq, sh);
    const float rstd = rsqrtf(sq * (1.0f / EMBED) + 1e-5f);

    float4 g = *(const float4*)&gamma[t * 4];
    float4 b = *(const float4*)&beta[t * 4];
    float4 o;
    o.x = dx * rstd * g.x + b.x;
    o.y = dy * rstd * g.y + b.y;
    o.z = dz * rstd * g.z + b.z;
    o.w = dw * rstd * g.w + b.w;
    *(float4*)&y[t * 4] = o;
}

// ================= launch =================
extern "C" void kernel_launch(void* const* d_in, const int* in_sizes, int n_in,
                              void* d_out, int out_size)
{
    const float* q_feat = (const float*)d_in[0];
    const float* kv     = (const float*)d_in[1];
    const float* Wq     = (const float*)d_in[2];
    const float* Wk     = (const float*)d_in[3];
    const float* Wv     = (const float*)d_in[4];
    const float* Wo     = (const float*)d_in[5];
    const float* bo     = (const float*)d_in[6];
    const float* Wfc    = (const float*)d_in[7];
    const float* gamma  = (const float*)d_in[8];
    const float* beta   = (const float*)d_in[9];
    float* out = (float*)d_out;

    bf16 *qfh, *kvh, *Qh, *Kh, *VT, *S, *Ch, *O1s, *Wq1, *Wk1, *Wv1, *Wo1, *Wfc3;
    float *Zi, *O2;
    cudaGetSymbolAddress((void**)&qfh,  g_qfh);
    cudaGetSymbolAddress((void**)&kvh,  g_kvh);
    cudaGetSymbolAddress((void**)&Qh,   g_Qh);
    cudaGetSymbolAddress((void**)&Kh,   g_Kh);
    cudaGetSymbolAddress((void**)&VT,   g_VT);
    cudaGetSymbolAddress((void**)&S,    g_S);
    cudaGetSymbolAddress((void**)&Zi,   g_Zi);
    cudaGetSymbolAddress((void**)&Ch,   g_Ch);
    cudaGetSymbolAddress((void**)&O1s,  g_O1s);
    cudaGetSymbolAddress((void**)&O2,   g_O2);
    cudaGetSymbolAddress((void**)&Wq1,  g_Wq1);
    cudaGetSymbolAddress((void**)&Wk1,  g_Wk1);
    cudaGetSymbolAddress((void**)&Wv1,  g_Wv1);
    cudaGetSymbolAddress((void**)&Wo1,  g_Wo1);
    cudaGetSymbolAddress((void**)&Wfc3, g_Wfc3);

    cudaFuncSetAttribute(gemm_nt<0>, cudaFuncAttributeMaxDynamicSharedMemorySize, GSMEM);
    cudaFuncSetAttribute(gemm_nt<3>, cudaFuncAttributeMaxDynamicSharedMemorySize, GSMEM);
    cudaFuncSetAttribute(gemm_nt<4>, cudaFuncAttributeMaxDynamicSharedMemorySize, GSMEM);
    cudaFuncSetAttribute(gemm_nt<5>, cudaFuncAttributeMaxDynamicSharedMemorySize, GSMEM);
    cudaFuncSetAttribute(gemm_nt<6>, cudaFuncAttributeMaxDynamicSharedMemorySize, GSMEM);

    const dim3 blk(256);
    const dim3 tblk(32, 8);
    // exp(s/sqrt(512)) = 2^(s * escale2)
    const float escale2 = 0.044194173824159216f * 1.4426950408889634f;

    // launch 0,1: fp32 -> bf16 converts
    conv_hi<<<(MTOK * EMBED / 4) / 256, 256>>>(q_feat, qfh);
    conv_hi<<<(MTOK * EMBED / 4) / 256, 256>>>(kv, kvh);
    // launch 2: fused Wq/Wk/Wv transpose (hi)
    w3tr<<<dim3(HIDDEN/32, EMBED/32, 3), tblk>>>(Wq, Wk, Wv, Wq1, Wk1, Wv1,
                                                 EMBED, HIDDEN);
    // launch 3: Q = qf @ Wq (x1)
    gemm_nt<4><<<dim3(HIDDEN/256, MTOK/128, 1), blk, GSMEM>>>(
        qfh, Wq1, Qh, EMBED, EMBED, EMBED, HIDDEN, 0, 0, 0, nullptr, nullptr, 0, 0.f);
    // launch 4: K = kv @ Wk (x1)
    gemm_nt<4><<<dim3(HIDDEN/256, MTOK/128, 1), blk, GSMEM>>>(
        kvh, Wk1, Kh, EMBED, EMBED, EMBED, HIDDEN, 0, 0, 0, nullptr, nullptr, 0, 0.f);
    // launch 5 (profiled): S = exp2(Q K^T * escale2) per batch
    gemm_nt<6><<<dim3(SKV/256, SQ/128, NB), blk, GSMEM>>>(
        Qh, Kh, S, HIDDEN, HIDDEN, HIDDEN, SKV,
        (long long)SQ * HIDDEN, (long long)SKV * HIDDEN, (long long)SQ * SKV,
        nullptr, nullptr, 0, escale2);
    // launch 6: VT[h,t] = sum_e Wv1[h,e] * kvh[t,e]
    gemm_nt<4><<<dim3(MTOK/256, HIDDEN/128, 1), blk, GSMEM>>>(
        Wv1, kvh, VT, EMBED, EMBED, EMBED, MTOK, 0, 0, 0, nullptr, nullptr, 0, 0.f);
    // launch 7: row sums -> Zinv
    sumexp_kernel<<<MTOK, 256>>>(S, Zi);
    // launch 8: ctx = (S @ V) * Zinv per batch
    gemm_nt<5><<<dim3(HIDDEN/256, SQ/128, NB), blk, GSMEM>>>(
        S, VT, Ch, SKV, SKV, MTOK, HIDDEN,
        (long long)SQ * SKV, (long long)SQ, (long long)SQ * HIDDEN,
        Zi, nullptr, SQ, 0.f);
    // launch 9: Wo^T hi transpose
    w3tr<<<dim3(EMBED/32, HIDDEN/32, 1), tblk>>>(Wo, Wo, Wo, Wo1, Wo1, Wo1,
                                                 HIDDEN, EMBED);
    // launch 10: O1 = ctx @ Wo + bo + q_feat -> A-split x3
    gemm_nt<3><<<dim3(EMBED/256, MTOK/128, 1), blk, GSMEM>>>(
        Ch, Wo1, O1s, HIDDEN, HIDDEN, HIDDEN, EMBED, 0, 0, 0, bo, q_feat, 0, 0.f);
    // launch 11: Wfc B-split x3
    bsplit3_tr<<<dim3(EMBED/32, EMBED/32), tblk>>>(Wfc, Wfc3, EMBED, EMBED);
    // launch 12: O2 = O1 @ Wfc (x3) -> fp32
    gemm_nt<0><<<dim3(EMBED/256, MTOK/128, 1), blk, GSMEM>>>(
        O1s, Wfc3, O2, 3*EMBED, 3*EMBED, 3*EMBED, EMBED, 0, 0, 0, nullptr, nullptr, 0, 0.f);
    // launch 13: layernorm -> out
    layernorm_kernel<<<MTOK, 256>>>(O2, gamma, beta, out);
}

// round 7
// speedup vs baseline: 1.3210x; 1.3210x over previous
#include <cuda_runtime.h>
#include <cuda_fp16.h>
#include <cstdint>
#include <math.h>

#define EMBED  1024
#define HIDDEN 512
#define NB     4
#define SQ     4096
#define SKV    4096
#define MTOK   (NB * SQ)   // 16384

typedef __half  f16;
typedef __half2 f162;

// ---------------- scratch (static device arrays; no allocations) ----------------
__device__ f16  g_qfh [(size_t)MTOK * EMBED];        // fp16 q_feat
__device__ f16  g_kvh [(size_t)MTOK * EMBED];        // fp16 kv_feat
__device__ f16  g_Qh  [(size_t)MTOK * HIDDEN];       // fp16 Q
__device__ f16  g_Kh  [(size_t)MTOK * HIDDEN];       // fp16 K
__device__ f16  g_VT  [(size_t)HIDDEN * MTOK];       // fp16 V^T [H, tokens]
__device__ f16  g_S   [(size_t)NB * SQ * SKV];       // unnormalized exp-scores
__device__ float g_Zi [MTOK];                        // 1/rowsum
__device__ f16  g_Ch  [(size_t)MTOK * HIDDEN];       // fp16 ctx
__device__ f16  g_O1h [(size_t)MTOK * EMBED];        // fp16 O1 (ctx@Wo+bo+qf)
__device__ float g_O2 [(size_t)MTOK * EMBED];        // fp32 pre-LN
__device__ f16  g_Wq1 [(size_t)HIDDEN * EMBED];      // fp16 Wq^T
__device__ f16  g_Wk1 [(size_t)HIDDEN * EMBED];
__device__ f16  g_Wv1 [(size_t)HIDDEN * EMBED];
__device__ f16  g_Wo1 [(size_t)EMBED * HIDDEN];      // fp16 Wo^T
__device__ f16  g_Wfc1[(size_t)EMBED * EMBED];       // fp16 Wfc^T

// ================= helpers =================
__device__ __forceinline__ uint32_t smem_u32(const void* p) {
    return (uint32_t)__cvta_generic_to_shared((void*)p);
}
#define SWZ128(o) ((o) ^ (((o) >> 3) & 0x70))

__device__ __forceinline__ void cpa16(uint32_t s, const void* g) {
    asm volatile("cp.async.cg.shared.global [%0], [%1], 16;" :: "r"(s), "l"(g));
}
__device__ __forceinline__ void cpa_commit() {
    asm volatile("cp.async.commit_group;" ::: "memory");
}
template <int N> __device__ __forceinline__ void cpa_wait() {
    asm volatile("cp.async.wait_group %0;" :: "n"(N) : "memory");
}
__device__ __forceinline__ void ldsm_x4(uint32_t a, uint32_t& r0, uint32_t& r1,
                                        uint32_t& r2, uint32_t& r3) {
    asm volatile("ldmatrix.sync.aligned.m8n8.x4.shared.b16 {%0,%1,%2,%3}, [%4];"
                 : "=r"(r0), "=r"(r1), "=r"(r2), "=r"(r3) : "r"(a));
}
__device__ __forceinline__ void mma16816(float* c, const uint32_t* a, const uint32_t* b) {
    asm volatile("mma.sync.aligned.m16n8k16.row.col.f32.f16.f16.f32 "
                 "{%0,%1,%2,%3}, {%4,%5,%6,%7}, {%8,%9}, {%0,%1,%2,%3};"
                 : "+f"(c[0]), "+f"(c[1]), "+f"(c[2]), "+f"(c[3])
                 : "r"(a[0]), "r"(a[1]), "r"(a[2]), "r"(a[3]), "r"(b[0]), "r"(b[1]));
}
__device__ __forceinline__ float ex2_mufu(float t) {
    float r;
    asm("ex2.approx.f32 %0, %1;" : "=f"(r) : "f"(t));
    return r;
}

// ================= fp16 NT GEMM =================
// D[m,n] = sum_k A[m,k]*B[n,k]; A row-stride lda, B row-stride ldb (fp16, rm).
// CTA tile 128x128, warp tile 64x32, 8 warps, K-step 64, 3-stage cp.async, 2 CTA/SM.
// MODE 0: fp32 store
// MODE 3: +bias[col]+res[row,col] (fp32) -> fp16 store
// MODE 4: fp16 store
// MODE 5: acc * rowscale[z*sAux + r] -> fp16 store
// MODE 6: exp2(acc * escale2) -> fp16 store
#define STAGE_B 32768
#define GSMEM   (3 * STAGE_B)   // 98304

template <int MODE>
__global__ void __launch_bounds__(256, 2)
gemm_nt(const f16* __restrict__ Ag, const f16* __restrict__ Bg,
        void* __restrict__ Cg, int Kp, int lda, int ldb, int ldc,
        long long sA, long long sB, long long sC,
        const float* __restrict__ aux1, const float* __restrict__ aux2,
        long long sAux, float escale2)
{
    extern __shared__ char smc[];
    const uint32_t sm0 = smem_u32(smc);
    const int tid  = threadIdx.x;
    const int wid  = tid >> 5;
    const int lane = tid & 31;
    const int wm = wid >> 2;        // 0..1
    const int wn = wid & 3;         // 0..3
    const int m0 = blockIdx.y * 128;
    const int n0 = blockIdx.x * 128;

    Ag += (long long)blockIdx.z * sA;
    Bg += (long long)blockIdx.z * sB;

    const f16* Abase = Ag + (long long)m0 * lda;
    const f16* Bbase = Bg + (long long)n0 * ldb;

    const int crow = tid >> 3;          // 0..31 base row
    const int ccol = tid & 7;           // 16B chunk

    float acc[4][4][4];
    #pragma unroll
    for (int a = 0; a < 4; a++)
        #pragma unroll
        for (int b = 0; b < 4; b++)
            #pragma unroll
            for (int c = 0; c < 4; c++) acc[a][b][c] = 0.0f;

    const int KT = Kp >> 6;

    auto load_stage = [&](int st, int kt) {
        const uint32_t sa = sm0 + st * STAGE_B;
        const uint32_t sb = sa + 16384;
        const int kofs = kt * 64;
        #pragma unroll
        for (int i = 0; i < 4; i++) {
            const int row = crow + i * 32;
            const uint32_t soff = SWZ128((uint32_t)(row * 128 + ccol * 16));
            cpa16(sa + soff, Abase + (long long)row * lda + kofs + ccol * 8);
            cpa16(sb + soff, Bbase + (long long)row * ldb + kofs + ccol * 8);
        }
    };

    load_stage(0, 0); cpa_commit();
    load_stage(1, 1); cpa_commit();

    int st = 0;
    for (int kt = 0; kt < KT; ++kt) {
        cpa_wait<1>();
        __syncthreads();

        const uint32_t sa = sm0 + st * STAGE_B;
        const uint32_t sb = sa + 16384;

        #pragma unroll
        for (int ks = 0; ks < 4; ks++) {
            uint32_t afr[4][4];
            uint32_t bfr[4][2];
            const int bcol = ks * 32 + ((lane >> 4) << 4);
            #pragma unroll
            for (int mt = 0; mt < 4; mt++) {
                const int row = wm * 64 + mt * 16 + (lane & 15);
                ldsm_x4(sa + SWZ128((uint32_t)(row * 128 + bcol)),
                        afr[mt][0], afr[mt][1], afr[mt][2], afr[mt][3]);
            }
            #pragma unroll
            for (int np = 0; np < 2; np++) {
                const int row = wn * 32 + np * 16 + (lane & 15);
                uint32_t r0, r1, r2, r3;
                ldsm_x4(sb + SWZ128((uint32_t)(row * 128 + bcol)), r0, r1, r2, r3);
                bfr[2*np][0] = r0;   bfr[2*np][1] = r2;
                bfr[2*np+1][0] = r1; bfr[2*np+1][1] = r3;
            }
            #pragma unroll
            for (int mt = 0; mt < 4; mt++)
                #pragma unroll
                for (int nt = 0; nt < 4; nt++)
                    mma16816(acc[mt][nt], afr[mt], bfr[nt]);
        }

        if (kt + 2 < KT) {
            int nst = st + 2; if (nst >= 3) nst -= 3;
            load_stage(nst, kt + 2);
        }
        cpa_commit();
        if (++st == 3) st = 0;
    }

    // -------- epilogue --------
    const float* rs = (MODE == 5) ? (aux1 + (long long)blockIdx.z * sAux) : nullptr;

    #pragma unroll
    for (int mt = 0; mt < 4; mt++) {
        const int r0 = m0 + wm * 64 + mt * 16 + (lane >> 2);
        const int r1 = r0 + 8;
        float rs0 = 1.0f, rs1 = 1.0f;
        if (MODE == 5) { rs0 = rs[r0]; rs1 = rs[r1]; }
        #pragma unroll
        for (int nt = 0; nt < 4; nt++) {
            const int c = n0 + wn * 32 + nt * 8 + (lane & 3) * 2;
            float x0 = acc[mt][nt][0], y0 = acc[mt][nt][1];
            float x1 = acc[mt][nt][2], y1 = acc[mt][nt][3];
            if (MODE == 5) { x0 *= rs0; y0 *= rs0; x1 *= rs1; y1 *= rs1; }
            if (MODE == 6) {
                x0 = ex2_mufu(x0 * escale2); y0 = ex2_mufu(y0 * escale2);
                x1 = ex2_mufu(x1 * escale2); y1 = ex2_mufu(y1 * escale2);
            }
            if (MODE == 3) {
                const float2 bv = *(const float2*)&aux1[c];
                const float2 q0 = *(const float2*)&aux2[(long long)r0 * ldc + c];
                const float2 q1 = *(const float2*)&aux2[(long long)r1 * ldc + c];
                x0 += bv.x + q0.x; y0 += bv.y + q0.y;
                x1 += bv.x + q1.x; y1 += bv.y + q1.y;
            }
            if (MODE == 0) {
                float* Cf = (float*)Cg + (long long)blockIdx.z * sC;
                *(float2*)&Cf[(long long)r0 * ldc + c] = make_float2(x0, y0);
                *(float2*)&Cf[(long long)r1 * ldc + c] = make_float2(x1, y1);
            } else {
                f16* Cb = (f16*)Cg + (long long)blockIdx.z * sC;
                *(f162*)&Cb[(long long)r0 * ldc + c] = __floats2half2_rn(x0, y0);
                *(f162*)&Cb[(long long)r1 * ldc + c] = __floats2half2_rn(x1, y1);
            }
        }
    }
}

// ============ fp32 -> fp16 convert (elementwise) ============
__global__ void conv_hi(const float* __restrict__ X, f16* __restrict__ Y)
{
    const long long i4 = (long long)blockIdx.x * blockDim.x + threadIdx.x;
    float4 v = ((const float4*)X)[i4];
    ((f162*)Y)[i4 * 2]     = __floats2half2_rn(v.x, v.y);
    ((f162*)Y)[i4 * 2 + 1] = __floats2half2_rn(v.z, v.w);
}

// ============ transpose + fp16: In[R,C] fp32 -> Out[C,R] fp16 ============
__global__ void w3tr(const float* __restrict__ A0, const float* __restrict__ A1,
                     const float* __restrict__ A2,
                     f16* __restrict__ B0, f16* __restrict__ B1,
                     f16* __restrict__ B2, int R, int C)
{
    const float* In = (blockIdx.z == 0) ? A0 : (blockIdx.z == 1) ? A1 : A2;
    f16* Out = (blockIdx.z == 0) ? B0 : (blockIdx.z == 1) ? B1 : B2;
    __shared__ float t[32][33];
    const int bx = blockIdx.x * 32;   // C
    const int by = blockIdx.y * 32;   // R
    const int tx = threadIdx.x, ty = threadIdx.y;
    #pragma unroll
    for (int i = ty; i < 32; i += 8)
        t[i][tx] = In[(long long)(by + i) * C + bx + tx];
    __syncthreads();
    #pragma unroll
    for (int i = ty; i < 32; i += 8)
        Out[(long long)(bx + i) * R + by + tx] = __float2half_rn(t[tx][i]);
}

// ================= reductions =================
__device__ __forceinline__ float blockReduceSum(float v, float* sh)
{
    const int t = threadIdx.x;
    #pragma unroll
    for (int o = 16; o; o >>= 1) v += __shfl_xor_sync(0xFFFFFFFFu, v, o);
    if ((t & 31) == 0) sh[t >> 5] = v;
    __syncthreads();
    if (t < 32) {
        float r = (t < 8) ? sh[t] : 0.0f;
        #pragma unroll
        for (int o = 4; o; o >>= 1) r += __shfl_xor_sync(0xFFFFFFFFu, r, o);
        if (t == 0) sh[0] = r;
    }
    __syncthreads();
    float r = sh[0];
    __syncthreads();
    return r;
}

// ===== row sums of unnormalized exp-scores -> Zinv =====
__global__ void sumexp_kernel(const f16* __restrict__ S, float* __restrict__ Zi)
{
    const f162* p = (const f162*)(S + (long long)blockIdx.x * SKV);
    const int t = threadIdx.x;
    __shared__ float sh[32];
    float s = 0.0f;
    #pragma unroll
    for (int i = 0; i < 8; i++) {
        float2 v = __half22float2(p[t + 256 * i]);
        s += v.x + v.y;
    }
    s = blockReduceSum(s, sh);
    if (t == 0) Zi[blockIdx.x] = 1.0f / s;
}

// ================= layernorm =================
__global__ void layernorm_kernel(const float* __restrict__ X,
                                 const float* __restrict__ gamma,
                                 const float* __restrict__ beta,
                                 float* __restrict__ Y)
{
    const float* x = X + (long long)blockIdx.x * EMBED;
    float*       y = Y + (long long)blockIdx.x * EMBED;
    const int t = threadIdx.x;
    __shared__ float sh[32];

    float4 v = *(const float4*)&x[t * 4];
    float s = v.x + v.y + v.z + v.w;
    s = blockReduceSum(s, sh);
    const float mu = s * (1.0f / EMBED);

    float dx = v.x - mu, dy = v.y - mu, dz = v.z - mu, dw = v.w - mu;
    float sq = dx * dx + dy * dy + dz * dz + dw * dw;
    sq = blockReduceSum(sq, sh);
    const float rstd = rsqrtf(sq * (1.0f / EMBED) + 1e-5f);

    float4 g = *(const float4*)&gamma[t * 4];
    float4 b = *(const float4*)&beta[t * 4];
    float4 o;
    o.x = dx * rstd * g.x + b.x;
    o.y = dy * rstd * g.y + b.y;
    o.z = dz * rstd * g.z + b.z;
    o.w = dw * rstd * g.w + b.w;
    *(float4*)&y[t * 4] = o;
}

// ================= launch =================
extern "C" void kernel_launch(void* const* d_in, const int* in_sizes, int n_in,
                              void* d_out, int out_size)
{
    const float* q_feat = (const float*)d_in[0];
    const float* kv     = (const float*)d_in[1];
    const float* Wq     = (const float*)d_in[2];
    const float* Wk     = (const float*)d_in[3];
    const float* Wv     = (const float*)d_in[4];
    const float* Wo     = (const float*)d_in[5];
    const float* bo     = (const float*)d_in[6];
    const float* Wfc    = (const float*)d_in[7];
    const float* gamma  = (const float*)d_in[8];
    const float* beta   = (const float*)d_in[9];
    float* out = (float*)d_out;

    f16 *qfh, *kvh, *Qh, *Kh, *VT, *S, *Ch, *O1h, *Wq1, *Wk1, *Wv1, *Wo1, *Wfc1;
    float *Zi, *O2;
    cudaGetSymbolAddress((void**)&qfh,  g_qfh);
    cudaGetSymbolAddress((void**)&kvh,  g_kvh);
    cudaGetSymbolAddress((void**)&Qh,   g_Qh);
    cudaGetSymbolAddress((void**)&Kh,   g_Kh);
    cudaGetSymbolAddress((void**)&VT,   g_VT);
    cudaGetSymbolAddress((void**)&S,    g_S);
    cudaGetSymbolAddress((void**)&Zi,   g_Zi);
    cudaGetSymbolAddress((void**)&Ch,   g_Ch);
    cudaGetSymbolAddress((void**)&O1h,  g_O1h);
    cudaGetSymbolAddress((void**)&O2,   g_O2);
    cudaGetSymbolAddress((void**)&Wq1,  g_Wq1);
    cudaGetSymbolAddress((void**)&Wk1,  g_Wk1);
    cudaGetSymbolAddress((void**)&Wv1,  g_Wv1);
    cudaGetSymbolAddress((void**)&Wo1,  g_Wo1);
    cudaGetSymbolAddress((void**)&Wfc1, g_Wfc1);

    cudaFuncSetAttribute(gemm_nt<0>, cudaFuncAttributeMaxDynamicSharedMemorySize, GSMEM);
    cudaFuncSetAttribute(gemm_nt<3>, cudaFuncAttributeMaxDynamicSharedMemorySize, GSMEM);
    cudaFuncSetAttribute(gemm_nt<4>, cudaFuncAttributeMaxDynamicSharedMemorySize, GSMEM);
    cudaFuncSetAttribute(gemm_nt<5>, cudaFuncAttributeMaxDynamicSharedMemorySize, GSMEM);
    cudaFuncSetAttribute(gemm_nt<6>, cudaFuncAttributeMaxDynamicSharedMemorySize, GSMEM);

    const dim3 blk(256);
    const dim3 tblk(32, 8);
    // exp(s/sqrt(512)) = 2^(s * escale2)
    const float escale2 = 0.044194173824159216f * 1.4426950408889634f;

    // launch 0,1: fp32 -> fp16 converts
    conv_hi<<<(MTOK * EMBED / 4) / 256, 256>>>(q_feat, qfh);
    conv_hi<<<(MTOK * EMBED / 4) / 256, 256>>>(kv, kvh);
    // launch 2: fused Wq/Wk/Wv transpose
    w3tr<<<dim3(HIDDEN/32, EMBED/32, 3), tblk>>>(Wq, Wk, Wv, Wq1, Wk1, Wv1,
                                                 EMBED, HIDDEN);
    // launch 3: Q = qf @ Wq
    gemm_nt<4><<<dim3(HIDDEN/128, MTOK/128, 1), blk, GSMEM>>>(
        qfh, Wq1, Qh, EMBED, EMBED, EMBED, HIDDEN, 0, 0, 0, nullptr, nullptr, 0, 0.f);
    // launch 4: K = kv @ Wk
    gemm_nt<4><<<dim3(HIDDEN/128, MTOK/128, 1), blk, GSMEM>>>(
        kvh, Wk1, Kh, EMBED, EMBED, EMBED, HIDDEN, 0, 0, 0, nullptr, nullptr, 0, 0.f);
    // launch 5 (profiled): S = exp2(Q K^T * escale2) per batch
    gemm_nt<6><<<dim3(SKV/128, SQ/128, NB), blk, GSMEM>>>(
        Qh, Kh, S, HIDDEN, HIDDEN, HIDDEN, SKV,
        (long long)SQ * HIDDEN, (long long)SKV * HIDDEN, (long long)SQ * SKV,
        nullptr, nullptr, 0, escale2);
    // launch 6: VT[h,t] = sum_e Wv1[h,e] * kvh[t,e]
    gemm_nt<4><<<dim3(MTOK/128, HIDDEN/128, 1), blk, GSMEM>>>(
        Wv1, kvh, VT, EMBED, EMBED, EMBED, MTOK, 0, 0, 0, nullptr, nullptr, 0, 0.f);
    // launch 7: row sums -> Zinv
    sumexp_kernel<<<MTOK, 256>>>(S, Zi);
    // launch 8: ctx = (S @ V) * Zinv per batch
    gemm_nt<5><<<dim3(HIDDEN/128, SQ/128, NB), blk, GSMEM>>>(
        S, VT, Ch, SKV, SKV, MTOK, HIDDEN,
        (long long)SQ * SKV, (long long)SQ, (long long)SQ * HIDDEN,
        Zi, nullptr, SQ, 0.f);
    // launch 9: Wo^T transpose
    w3tr<<<dim3(EMBED/32, HIDDEN/32, 1), tblk>>>(Wo, Wo, Wo, Wo1, Wo1, Wo1,
                                                 HIDDEN, EMBED);
    // launch 10: O1 = ctx @ Wo + bo + q_feat -> fp16
    gemm_nt<3><<<dim3(EMBED/128, MTOK/128, 1), blk, GSMEM>>>(
        Ch, Wo1, O1h, HIDDEN, HIDDEN, HIDDEN, EMBED, 0, 0, 0, bo, q_feat, 0, 0.f);
    // launch 11: Wfc^T transpose
    w3tr<<<dim3(EMBED/32, EMBED/32, 1), tblk>>>(Wfc, Wfc, Wfc, Wfc1, Wfc1, Wfc1,
                                                EMBED, EMBED);
    // launch 12: O2 = O1 @ Wfc -> fp32
    gemm_nt<0><<<dim3(EMBED/128, MTOK/128, 1), blk, GSMEM>>>(
        O1h, Wfc1, O2, EMBED, EMBED, EMBED, EMBED, 0, 0, 0, nullptr, nullptr, 0, 0.f);
    // launch 13: layernorm -> out
    layernorm_kernel<<<MTOK, 256>>>(O2, gamma, beta, out);
}